// round 8
// baseline (speedup 1.0000x reference)
#include <cuda_runtime.h>
#include <cuda_bf16.h>

#define N_NODES 50000
#define E_EDGES 800000
#define D 64
#define NC 40
#define RB 128            // rows per block in GEMM kernels
#define EPT 8             // edges per thread-chunk in sorted scatter (800000 % 8 == 0)

// Scratch (allocation-free rule: __device__ globals). 16B-aligned for float4 access.
__device__ __align__(16) float g_dinv[N_NODES];
__device__ __align__(16) float g_hs [N_NODES * D];   // pre-scaled transformed features
__device__ __align__(16) float g_agg[N_NODES * D];   // aggregation target
__device__ int  g_cnt   [N_NODES];                   // in-degree (excl self)
__device__ int  g_cursor[N_NODES];                   // fill cursors
__device__ __align__(8) int2 g_epair[E_EDGES];       // dst-sorted (src, dst) pairs

// ---------------------------------------------------------------------------
// Build: count -> scan (rowptr/cursor/dinv) -> fill (dst-sorted edge pairs)
// ---------------------------------------------------------------------------
__global__ void k_zero_cnt() {
    int i = blockIdx.x * blockDim.x + threadIdx.x;
    if (i < N_NODES) g_cnt[i] = 0;
}

__global__ void k_count(const int* __restrict__ dst) {
    int e = blockIdx.x * blockDim.x + threadIdx.x;
    if (e < E_EDGES) atomicAdd(&g_cnt[dst[e]], 1);
}

// Single-block exclusive scan over 50k ints; writes cursor start + dinv.
__global__ void k_scan() {
    __shared__ int s[1024];
    const int PER = (N_NODES + 1023) / 1024;   // 49
    int t = threadIdx.x;
    int base = t * PER;
    int sum = 0;
    #pragma unroll 4
    for (int i = 0; i < PER; i++) {
        int idx = base + i;
        if (idx < N_NODES) sum += g_cnt[idx];
    }
    s[t] = sum;
    __syncthreads();
    for (int off = 1; off < 1024; off <<= 1) {
        int v = (t >= off) ? s[t - off] : 0;
        __syncthreads();
        s[t] += v;
        __syncthreads();
    }
    int run = s[t] - sum;   // exclusive prefix of this thread's chunk
    #pragma unroll 4
    for (int i = 0; i < PER; i++) {
        int idx = base + i;
        if (idx < N_NODES) {
            g_cursor[idx] = run;
            int c = g_cnt[idx];
            g_dinv[idx] = rsqrtf((float)(c + 1));   // +1 self-loop
            run += c;
        }
    }
}

__global__ void k_fill(const int* __restrict__ src, const int* __restrict__ dst) {
    int e = blockIdx.x * blockDim.x + threadIdx.x;
    if (e < E_EDGES) {
        int d = dst[e];
        int p = atomicAdd(&g_cursor[d], 1);
        g_epair[p] = make_int2(src[e], d);
    }
}

// ---------------------------------------------------------------------------
// Layer-1 GEMM: hs = (x @ W1) * dinv[row]; agg = hs (self-loop term)
// 128 rows/block, 256 threads, 8x4 register tile per thread.
// ---------------------------------------------------------------------------
__global__ void k_gemm1(const float* __restrict__ x, const float* __restrict__ W1) {
    __shared__ float sW[D][D];
    __shared__ float sx[RB][D];
    int tid = threadIdx.x;
    int row0 = blockIdx.x * RB;

    #pragma unroll
    for (int i = 0; i < 4; i++) {
        int idx = tid * 4 + i * 1024;
        *reinterpret_cast<float4*>(&sW[0][0] + idx) =
            *reinterpret_cast<const float4*>(W1 + idx);
    }
    #pragma unroll
    for (int i = 0; i < 8; i++) {
        int lin = tid + i * 256;
        int r = lin >> 4;
        int c4 = (lin & 15) * 4;
        int row = row0 + r;
        float4 v = make_float4(0.f, 0.f, 0.f, 0.f);
        if (row < N_NODES) v = *reinterpret_cast<const float4*>(x + (size_t)row * D + c4);
        *reinterpret_cast<float4*>(&sx[r][c4]) = v;
    }
    __syncthreads();

    int tc = tid & 15;
    int tr = tid >> 4;
    float4 acc[8];
    #pragma unroll
    for (int i = 0; i < 8; i++) acc[i] = make_float4(0.f, 0.f, 0.f, 0.f);
    #pragma unroll
    for (int k = 0; k < D; k++) {
        float4 w = *reinterpret_cast<float4*>(&sW[k][tc * 4]);
        #pragma unroll
        for (int i = 0; i < 8; i++) {
            float xv = sx[tr * 8 + i][k];
            acc[i].x = fmaf(xv, w.x, acc[i].x);
            acc[i].y = fmaf(xv, w.y, acc[i].y);
            acc[i].z = fmaf(xv, w.z, acc[i].z);
            acc[i].w = fmaf(xv, w.w, acc[i].w);
        }
    }
    #pragma unroll
    for (int i = 0; i < 8; i++) {
        int row = row0 + tr * 8 + i;
        if (row < N_NODES) {
            float di = g_dinv[row];
            float4 v = make_float4(acc[i].x * di, acc[i].y * di, acc[i].z * di, acc[i].w * di);
            *reinterpret_cast<float4*>(g_hs  + (size_t)row * D + tc * 4) = v;
            *reinterpret_cast<float4*>(g_agg + (size_t)row * D + tc * 4) = v;
        }
    }
}

// ---------------------------------------------------------------------------
// Sorted scatter: each thread handles one float4 column of EPT consecutive
// dst-sorted edges. Gathers are issued with MLP=EPT, runs sharing dst are
// combined in registers -> ~4-8x fewer atomics than edge-per-thread.
// ---------------------------------------------------------------------------
__global__ void k_scatter_sorted() {
    long long idx = (long long)blockIdx.x * blockDim.x + threadIdx.x;
    int chunk = (int)(idx >> 4);         // group of EPT edges
    int col   = (int)(idx & 15);         // float4 column 0..15
    int e0 = chunk * EPT;
    if (e0 >= E_EDGES) return;

    const float4* hs4  = reinterpret_cast<const float4*>(g_hs);
    float4*       agg4 = reinterpret_cast<float4*>(g_agg);

    int2 pr[EPT];
    #pragma unroll
    for (int i = 0; i < EPT; i++) pr[i] = g_epair[e0 + i];   // broadcast in half-warp

    float4 vals[EPT];
    #pragma unroll
    for (int i = 0; i < EPT; i++)
        vals[i] = hs4[(size_t)pr[i].x * 16 + col];           // 8 independent gathers

    int cur_d = pr[0].y;
    float4 acc = vals[0];
    #pragma unroll
    for (int i = 1; i < EPT; i++) {
        int d = pr[i].y;
        if (d != cur_d) {
            atomicAdd(&agg4[(size_t)cur_d * 16 + col], acc);
            cur_d = d;
            acc = vals[i];
        } else {
            acc.x += vals[i].x; acc.y += vals[i].y;
            acc.z += vals[i].z; acc.w += vals[i].w;
        }
    }
    atomicAdd(&agg4[(size_t)cur_d * 16 + col], acc);
}

// ---------------------------------------------------------------------------
// Fused: h1 = tanh(agg * dinv + b1); hs = (h1 @ W2) * dinv; agg = hs
// ---------------------------------------------------------------------------
__global__ void k_layer2(const float* __restrict__ W2, const float* __restrict__ b1) {
    __shared__ float sW[D][D];
    __shared__ float st[RB][D];
    int tid = threadIdx.x;
    int row0 = blockIdx.x * RB;

    #pragma unroll
    for (int i = 0; i < 4; i++) {
        int idx = tid * 4 + i * 1024;
        *reinterpret_cast<float4*>(&sW[0][0] + idx) =
            *reinterpret_cast<const float4*>(W2 + idx);
    }
    #pragma unroll
    for (int i = 0; i < 8; i++) {
        int lin = tid + i * 256;
        int r = lin >> 4;
        int c4 = (lin & 15) * 4;
        int row = row0 + r;
        float4 v = make_float4(0.f, 0.f, 0.f, 0.f);
        if (row < N_NODES) {
            float di = g_dinv[row];
            float4 a = *reinterpret_cast<const float4*>(g_agg + (size_t)row * D + c4);
            float4 b = *reinterpret_cast<const float4*>(b1 + c4);
            v.x = tanhf(fmaf(a.x, di, b.x));
            v.y = tanhf(fmaf(a.y, di, b.y));
            v.z = tanhf(fmaf(a.z, di, b.z));
            v.w = tanhf(fmaf(a.w, di, b.w));
        }
        *reinterpret_cast<float4*>(&st[r][c4]) = v;
    }
    __syncthreads();

    int tc = tid & 15;
    int tr = tid >> 4;
    float4 acc[8];
    #pragma unroll
    for (int i = 0; i < 8; i++) acc[i] = make_float4(0.f, 0.f, 0.f, 0.f);
    #pragma unroll
    for (int k = 0; k < D; k++) {
        float4 w = *reinterpret_cast<float4*>(&sW[k][tc * 4]);
        #pragma unroll
        for (int i = 0; i < 8; i++) {
            float xv = st[tr * 8 + i][k];
            acc[i].x = fmaf(xv, w.x, acc[i].x);
            acc[i].y = fmaf(xv, w.y, acc[i].y);
            acc[i].z = fmaf(xv, w.z, acc[i].z);
            acc[i].w = fmaf(xv, w.w, acc[i].w);
        }
    }
    #pragma unroll
    for (int i = 0; i < 8; i++) {
        int row = row0 + tr * 8 + i;
        if (row < N_NODES) {
            float di = g_dinv[row];
            float4 v = make_float4(acc[i].x * di, acc[i].y * di, acc[i].z * di, acc[i].w * di);
            *reinterpret_cast<float4*>(g_hs  + (size_t)row * D + tc * 4) = v;
            *reinterpret_cast<float4*>(g_agg + (size_t)row * D + tc * 4) = v;
        }
    }
}

// ---------------------------------------------------------------------------
// Fused final: h = tanh(agg * dinv + b2)  -> d_out[N*NC ..]  (h output)
//              out = h @ Wc + bc          -> d_out[0 .. N*NC) (logits)
// ---------------------------------------------------------------------------
__global__ void k_final(const float* __restrict__ Wc, const float* __restrict__ b2,
                        const float* __restrict__ bc, float* __restrict__ out) {
    __shared__ float sW[D][NC];
    __shared__ float st[RB][D];
    int tid = threadIdx.x;
    int row0 = blockIdx.x * RB;

    #pragma unroll
    for (int i = 0; i < 3; i++) {
        int f4 = tid + i * 256;
        if (f4 < D * NC / 4)
            *(reinterpret_cast<float4*>(&sW[0][0]) + f4) =
                *(reinterpret_cast<const float4*>(Wc) + f4);
    }
    #pragma unroll
    for (int i = 0; i < 8; i++) {
        int lin = tid + i * 256;
        int r = lin >> 4;
        int c4 = (lin & 15) * 4;
        int row = row0 + r;
        float4 v = make_float4(0.f, 0.f, 0.f, 0.f);
        if (row < N_NODES) {
            float di = g_dinv[row];
            float4 a = *reinterpret_cast<const float4*>(g_agg + (size_t)row * D + c4);
            float4 b = *reinterpret_cast<const float4*>(b2 + c4);
            v.x = tanhf(fmaf(a.x, di, b.x));
            v.y = tanhf(fmaf(a.y, di, b.y));
            v.z = tanhf(fmaf(a.z, di, b.z));
            v.w = tanhf(fmaf(a.w, di, b.w));
            *reinterpret_cast<float4*>(out + (size_t)N_NODES * NC + (size_t)row * D + c4) = v;
        }
        *reinterpret_cast<float4*>(&st[r][c4]) = v;
    }
    __syncthreads();

    int tc = tid & 15;
    int tr = tid >> 4;
    if (tc < NC / 4) {
        float4 bcv = *reinterpret_cast<const float4*>(bc + tc * 4);
        float4 acc[8];
        #pragma unroll
        for (int i = 0; i < 8; i++) acc[i] = bcv;
        #pragma unroll
        for (int k = 0; k < D; k++) {
            float4 w = *reinterpret_cast<float4*>(&sW[k][tc * 4]);
            #pragma unroll
            for (int i = 0; i < 8; i++) {
                float xv = st[tr * 8 + i][k];
                acc[i].x = fmaf(xv, w.x, acc[i].x);
                acc[i].y = fmaf(xv, w.y, acc[i].y);
                acc[i].z = fmaf(xv, w.z, acc[i].z);
                acc[i].w = fmaf(xv, w.w, acc[i].w);
            }
        }
        #pragma unroll
        for (int i = 0; i < 8; i++) {
            int row = row0 + tr * 8 + i;
            if (row < N_NODES)
                *reinterpret_cast<float4*>(out + (size_t)row * NC + tc * 4) = acc[i];
        }
    }
}

// ---------------------------------------------------------------------------
extern "C" void kernel_launch(void* const* d_in, const int* in_sizes, int n_in,
                              void* d_out, int out_size) {
    const float* x   = (const float*)d_in[0];
    const int*   ei  = (const int*)d_in[1];   // [2, E] int32 (JAX x64 disabled)
    const float* W1  = (const float*)d_in[2];
    const float* b1  = (const float*)d_in[3];
    const float* W2  = (const float*)d_in[4];
    const float* b2  = (const float*)d_in[5];
    const float* Wc  = (const float*)d_in[6];
    const float* bc  = (const float*)d_in[7];
    float* out = (float*)d_out;

    const int* src = ei;              // edge_index[0]
    const int* dst = ei + E_EDGES;    // edge_index[1]

    const int TB = 256;
    const int gN    = (N_NODES + TB - 1) / TB;
    const int gE    = (E_EDGES + TB - 1) / TB;
    const int gRows = (N_NODES + RB - 1) / RB;                     // 391
    const long long scatThreads = (long long)(E_EDGES / EPT) * 16; // 1.6M
    const int gScat = (int)((scatThreads + TB - 1) / TB);

    // Build dst-sorted edge list + dinv
    k_zero_cnt<<<gN, TB>>>();
    k_count   <<<gE, TB>>>(dst);
    k_scan    <<<1, 1024>>>();
    k_fill    <<<gE, TB>>>(src, dst);

    // Layer pipeline
    k_gemm1          <<<gRows, TB>>>(x, W1);
    k_scatter_sorted <<<gScat, TB>>>();
    k_layer2         <<<gRows, TB>>>(W2, b1);
    k_scatter_sorted <<<gScat, TB>>>();
    k_final          <<<gRows, TB>>>(Wc, b2, bc, out);
}

// round 9
// speedup vs baseline: 1.3756x; 1.3756x over previous
#include <cuda_runtime.h>
#include <cuda_bf16.h>
#include <cuda_fp16.h>

#define N_NODES 50000
#define E_EDGES 800000
#define D 64
#define NC 40
#define RB 128            // rows per block in GEMM kernels

// Scratch (allocation-free rule: __device__ globals). 16B-aligned for vector access.
__device__ __align__(16) float  g_dinv[N_NODES];         // deg, then rsqrt(deg)
__device__ __align__(16) __half g_hsh[N_NODES * D];      // fp16 copy of pre-scaled features
__device__ __align__(16) float  g_agg[N_NODES * D];      // fp32 aggregation target

// ---------------------------------------------------------------------------
// Degree: deg[i] = 1 (self-loop) + #edges with dst==i ; then dinv = rsqrt(deg)
// ---------------------------------------------------------------------------
__global__ void k_init_deg() {
    int i = blockIdx.x * blockDim.x + threadIdx.x;
    if (i < N_NODES) g_dinv[i] = 1.0f;
}

__global__ void k_count_deg(const int* __restrict__ dst) {
    int e = blockIdx.x * blockDim.x + threadIdx.x;
    if (e < E_EDGES) atomicAdd(&g_dinv[dst[e]], 1.0f);
}

__global__ void k_finish_dinv() {
    int i = blockIdx.x * blockDim.x + threadIdx.x;
    if (i < N_NODES) g_dinv[i] = rsqrtf(g_dinv[i]);
}

// ---------------------------------------------------------------------------
// Store helper: fp32 self-loop seed into agg, fp16 copy for scatter gathers
// ---------------------------------------------------------------------------
__device__ __forceinline__ void store_scaled(int row, int c4, float4 v) {
    *reinterpret_cast<float4*>(g_agg + (size_t)row * D + c4) = v;
    __half2 h01 = __floats2half2_rn(v.x, v.y);
    __half2 h23 = __floats2half2_rn(v.z, v.w);
    uint2 packed;
    packed.x = *reinterpret_cast<unsigned*>(&h01);
    packed.y = *reinterpret_cast<unsigned*>(&h23);
    *reinterpret_cast<uint2*>(g_hsh + (size_t)row * D + c4) = packed;
}

// ---------------------------------------------------------------------------
// Layer-1 GEMM: hs = (x @ W1) * dinv[row]; agg = hs (fp32); hsh = hs (fp16)
// 128 rows/block, 256 threads, 8x4 register tile per thread.
// ---------------------------------------------------------------------------
__global__ void k_gemm1(const float* __restrict__ x, const float* __restrict__ W1) {
    __shared__ float sW[D][D];
    __shared__ float sx[RB][D];
    int tid = threadIdx.x;
    int row0 = blockIdx.x * RB;

    #pragma unroll
    for (int i = 0; i < 4; i++) {
        int idx = tid * 4 + i * 1024;
        *reinterpret_cast<float4*>(&sW[0][0] + idx) =
            *reinterpret_cast<const float4*>(W1 + idx);
    }
    #pragma unroll
    for (int i = 0; i < 8; i++) {
        int lin = tid + i * 256;
        int r = lin >> 4;
        int c4 = (lin & 15) * 4;
        int row = row0 + r;
        float4 v = make_float4(0.f, 0.f, 0.f, 0.f);
        if (row < N_NODES) v = *reinterpret_cast<const float4*>(x + (size_t)row * D + c4);
        *reinterpret_cast<float4*>(&sx[r][c4]) = v;
    }
    __syncthreads();

    int tc = tid & 15;
    int tr = tid >> 4;
    float4 acc[8];
    #pragma unroll
    for (int i = 0; i < 8; i++) acc[i] = make_float4(0.f, 0.f, 0.f, 0.f);
    #pragma unroll
    for (int k = 0; k < D; k++) {
        float4 w = *reinterpret_cast<float4*>(&sW[k][tc * 4]);
        #pragma unroll
        for (int i = 0; i < 8; i++) {
            float xv = sx[tr * 8 + i][k];
            acc[i].x = fmaf(xv, w.x, acc[i].x);
            acc[i].y = fmaf(xv, w.y, acc[i].y);
            acc[i].z = fmaf(xv, w.z, acc[i].z);
            acc[i].w = fmaf(xv, w.w, acc[i].w);
        }
    }
    #pragma unroll
    for (int i = 0; i < 8; i++) {
        int row = row0 + tr * 8 + i;
        if (row < N_NODES) {
            float di = g_dinv[row];
            store_scaled(row, tc * 4,
                make_float4(acc[i].x * di, acc[i].y * di, acc[i].z * di, acc[i].w * di));
        }
    }
}

// ---------------------------------------------------------------------------
// Edge scatter: agg[dst] += hsh[src] (fp16 gather, fp32 float4 atomic).
// 16 lanes/edge: each gathers 4 halfs (8B, coalesced 128B/edge) -> 1 atomic.
// ---------------------------------------------------------------------------
__global__ void k_scatter(const int* __restrict__ src,
                          const int* __restrict__ dst) {
    long long idx = (long long)blockIdx.x * blockDim.x + threadIdx.x;
    int e = (int)(idx >> 4);
    int c = (int)(idx & 15);
    if (e >= E_EDGES) return;
    int s = src[e];
    int d = dst[e];
    uint2 p = reinterpret_cast<const uint2*>(g_hsh + (size_t)s * D)[c];
    __half2 h01 = *reinterpret_cast<__half2*>(&p.x);
    __half2 h23 = *reinterpret_cast<__half2*>(&p.y);
    float2 fa = __half22float2(h01);
    float2 fb = __half22float2(h23);
    atomicAdd(reinterpret_cast<float4*>(g_agg + (size_t)d * D) + c,
              make_float4(fa.x, fa.y, fb.x, fb.y));
}

// ---------------------------------------------------------------------------
// Fused: h1 = tanh(agg * dinv + b1); hs = (h1 @ W2) * dinv; agg/hsh = hs
// ---------------------------------------------------------------------------
__global__ void k_layer2(const float* __restrict__ W2, const float* __restrict__ b1) {
    __shared__ float sW[D][D];
    __shared__ float st[RB][D];
    int tid = threadIdx.x;
    int row0 = blockIdx.x * RB;

    #pragma unroll
    for (int i = 0; i < 4; i++) {
        int idx = tid * 4 + i * 1024;
        *reinterpret_cast<float4*>(&sW[0][0] + idx) =
            *reinterpret_cast<const float4*>(W2 + idx);
    }
    #pragma unroll
    for (int i = 0; i < 8; i++) {
        int lin = tid + i * 256;
        int r = lin >> 4;
        int c4 = (lin & 15) * 4;
        int row = row0 + r;
        float4 v = make_float4(0.f, 0.f, 0.f, 0.f);
        if (row < N_NODES) {
            float di = g_dinv[row];
            float4 a = *reinterpret_cast<const float4*>(g_agg + (size_t)row * D + c4);
            float4 b = *reinterpret_cast<const float4*>(b1 + c4);
            v.x = tanhf(fmaf(a.x, di, b.x));
            v.y = tanhf(fmaf(a.y, di, b.y));
            v.z = tanhf(fmaf(a.z, di, b.z));
            v.w = tanhf(fmaf(a.w, di, b.w));
        }
        *reinterpret_cast<float4*>(&st[r][c4]) = v;
    }
    __syncthreads();

    int tc = tid & 15;
    int tr = tid >> 4;
    float4 acc[8];
    #pragma unroll
    for (int i = 0; i < 8; i++) acc[i] = make_float4(0.f, 0.f, 0.f, 0.f);
    #pragma unroll
    for (int k = 0; k < D; k++) {
        float4 w = *reinterpret_cast<float4*>(&sW[k][tc * 4]);
        #pragma unroll
        for (int i = 0; i < 8; i++) {
            float xv = st[tr * 8 + i][k];
            acc[i].x = fmaf(xv, w.x, acc[i].x);
            acc[i].y = fmaf(xv, w.y, acc[i].y);
            acc[i].z = fmaf(xv, w.z, acc[i].z);
            acc[i].w = fmaf(xv, w.w, acc[i].w);
        }
    }
    #pragma unroll
    for (int i = 0; i < 8; i++) {
        int row = row0 + tr * 8 + i;
        if (row < N_NODES) {
            float di = g_dinv[row];
            store_scaled(row, tc * 4,
                make_float4(acc[i].x * di, acc[i].y * di, acc[i].z * di, acc[i].w * di));
        }
    }
}

// ---------------------------------------------------------------------------
// Fused final: h = tanh(agg * dinv + b2)  -> d_out[N*NC ..]  (h output)
//              out = h @ Wc + bc          -> d_out[0 .. N*NC) (logits)
// ---------------------------------------------------------------------------
__global__ void k_final(const float* __restrict__ Wc, const float* __restrict__ b2,
                        const float* __restrict__ bc, float* __restrict__ out) {
    __shared__ float sW[D][NC];
    __shared__ float st[RB][D];
    int tid = threadIdx.x;
    int row0 = blockIdx.x * RB;

    #pragma unroll
    for (int i = 0; i < 3; i++) {
        int f4 = tid + i * 256;
        if (f4 < D * NC / 4)
            *(reinterpret_cast<float4*>(&sW[0][0]) + f4) =
                *(reinterpret_cast<const float4*>(Wc) + f4);
    }
    #pragma unroll
    for (int i = 0; i < 8; i++) {
        int lin = tid + i * 256;
        int r = lin >> 4;
        int c4 = (lin & 15) * 4;
        int row = row0 + r;
        float4 v = make_float4(0.f, 0.f, 0.f, 0.f);
        if (row < N_NODES) {
            float di = g_dinv[row];
            float4 a = *reinterpret_cast<const float4*>(g_agg + (size_t)row * D + c4);
            float4 b = *reinterpret_cast<const float4*>(b2 + c4);
            v.x = tanhf(fmaf(a.x, di, b.x));
            v.y = tanhf(fmaf(a.y, di, b.y));
            v.z = tanhf(fmaf(a.z, di, b.z));
            v.w = tanhf(fmaf(a.w, di, b.w));
            *reinterpret_cast<float4*>(out + (size_t)N_NODES * NC + (size_t)row * D + c4) = v;
        }
        *reinterpret_cast<float4*>(&st[r][c4]) = v;
    }
    __syncthreads();

    int tc = tid & 15;
    int tr = tid >> 4;
    if (tc < NC / 4) {
        float4 bcv = *reinterpret_cast<const float4*>(bc + tc * 4);
        float4 acc[8];
        #pragma unroll
        for (int i = 0; i < 8; i++) acc[i] = bcv;
        #pragma unroll
        for (int k = 0; k < D; k++) {
            float4 w = *reinterpret_cast<float4*>(&sW[k][tc * 4]);
            #pragma unroll
            for (int i = 0; i < 8; i++) {
                float xv = st[tr * 8 + i][k];
                acc[i].x = fmaf(xv, w.x, acc[i].x);
                acc[i].y = fmaf(xv, w.y, acc[i].y);
                acc[i].z = fmaf(xv, w.z, acc[i].z);
                acc[i].w = fmaf(xv, w.w, acc[i].w);
            }
        }
        #pragma unroll
        for (int i = 0; i < 8; i++) {
            int row = row0 + tr * 8 + i;
            if (row < N_NODES)
                *reinterpret_cast<float4*>(out + (size_t)row * NC + tc * 4) = acc[i];
        }
    }
}

// ---------------------------------------------------------------------------
extern "C" void kernel_launch(void* const* d_in, const int* in_sizes, int n_in,
                              void* d_out, int out_size) {
    const float* x   = (const float*)d_in[0];
    const int*   ei  = (const int*)d_in[1];   // [2, E] int32 (JAX x64 disabled)
    const float* W1  = (const float*)d_in[2];
    const float* b1  = (const float*)d_in[3];
    const float* W2  = (const float*)d_in[4];
    const float* b2  = (const float*)d_in[5];
    const float* Wc  = (const float*)d_in[6];
    const float* bc  = (const float*)d_in[7];
    float* out = (float*)d_out;

    const int* src = ei;              // edge_index[0]
    const int* dst = ei + E_EDGES;    // edge_index[1]

    const int TB = 256;
    const int gN    = (N_NODES + TB - 1) / TB;
    const int gE    = (E_EDGES + TB - 1) / TB;
    const int gRows = (N_NODES + RB - 1) / RB;            // 391
    const long long scatterThreads = (long long)E_EDGES * 16;
    const int gScat = (int)((scatterThreads + TB - 1) / TB);

    k_init_deg   <<<gN, TB>>>();
    k_count_deg  <<<gE, TB>>>(dst);
    k_finish_dinv<<<gN, TB>>>();

    k_gemm1   <<<gRows, TB>>>(x, W1);
    k_scatter <<<gScat, TB>>>(src, dst);
    k_layer2  <<<gRows, TB>>>(W2, b1);
    k_scatter <<<gScat, TB>>>(src, dst);
    k_final   <<<gRows, TB>>>(Wc, b2, bc, out);
}